// round 2
// baseline (speedup 1.0000x reference)
#include <cuda_runtime.h>
#include <cuda_bf16.h>
#include <math.h>

// ---------------------------------------------------------------------------
// StarTransformer: B=8, L=2048, H=512, NH=8, HD=64, NUM_LAYERS=4
// ---------------------------------------------------------------------------
#define BB   8
#define LL   2048
#define LP1  2049
#define HH   512
#define NHD  8
#define HD   64
#define NL   4

// -------------------- scratch (device globals, no allocs) -------------------
__device__ float g_nodes[BB * LL * HH];     // (b,l,c)
__device__ float g_xy  [BB * LP1 * HH];     // (b,l,c) with relay at l=2048
__device__ float g_q   [BB * LP1 * HH];
__device__ float g_k   [BB * LP1 * HH];
__device__ float g_v   [BB * LP1 * HH];
__device__ float g_relay[BB * HH];
__device__ float g_attr [BB * HH];
__device__ float g_part [BB * 16 * HH];
// att reuses g_xy?  No: keep separate to stay safe.
__device__ float g_att [BB * LL * HH];

// compile-time scratch selector (avoids any host-side symbol-address API)
#define BUF_PARAM (-1)
#define BUF_NODES 0
#define BUF_XY    1
#define BUF_Q     2
#define BUF_K     3
#define BUF_V     4
#define BUF_ATT   5

template<int ID>
__device__ __forceinline__ float* sbuf() {
    if constexpr (ID == BUF_NODES) return g_nodes;
    else if constexpr (ID == BUF_XY)  return g_xy;
    else if constexpr (ID == BUF_Q)   return g_q;
    else if constexpr (ID == BUF_K)   return g_k;
    else if constexpr (ID == BUF_V)   return g_v;
    else if constexpr (ID == BUF_ATT) return g_att;
    else return nullptr;
}

// ---------------------------- tiled SGEMM body ------------------------------
// C[M x 512] = A[M x 512] @ W[512 x 512]  (+ epilogue)
// EPI 0: + bias[c]
// EPI 1: + bias[c] + pos[(r % 2048)*512 + c]
// EPI 2: leaky_relu( + bias[c], 0.2)
#define BM 128
#define BN 128
#define BK 8

template<int EPI>
__device__ __forceinline__
void sgemm_body(const float* __restrict__ A, const float* __restrict__ W,
                float* __restrict__ C, int M,
                const float* __restrict__ bias, const float* __restrict__ pos)
{
    __shared__ float As[2][BK][BM];
    __shared__ float Bs[2][BK][BN];

    const int tid  = threadIdx.x;
    const int row0 = blockIdx.y * BM;
    const int col0 = blockIdx.x * BN;

    // global load mapping
    const int a_r = tid >> 1;          // 0..127
    const int a_c = (tid & 1) * 4;     // 0 or 4
    const int b_r = tid >> 5;          // 0..7
    const int b_c = (tid & 31) * 4;    // 0..124

    // compute mapping (16 x 16 threads, 8x8 microtile split 4+4)
    const int tx = tid & 15;
    const int ty = tid >> 4;

    float acc[8][8];
    #pragma unroll
    for (int i = 0; i < 8; ++i)
        #pragma unroll
        for (int j = 0; j < 8; ++j) acc[i][j] = 0.f;

    float4 a_tmp, b_tmp;
    // prologue: tile 0
    {
        const int gr = row0 + a_r;
        a_tmp = (gr < M) ? *(const float4*)(A + (size_t)gr * HH + a_c)
                         : make_float4(0.f, 0.f, 0.f, 0.f);
        b_tmp = *(const float4*)(W + (size_t)b_r * HH + col0 + b_c);
        As[0][a_c + 0][a_r] = a_tmp.x;
        As[0][a_c + 1][a_r] = a_tmp.y;
        As[0][a_c + 2][a_r] = a_tmp.z;
        As[0][a_c + 3][a_r] = a_tmp.w;
        *(float4*)&Bs[0][b_r][b_c] = b_tmp;
    }
    __syncthreads();

    const int NT = HH / BK;   // 64
    for (int kt = 0; kt < NT; ++kt) {
        const int cur = kt & 1;
        if (kt + 1 < NT) {
            const int kb = (kt + 1) * BK;
            const int gr = row0 + a_r;
            a_tmp = (gr < M) ? *(const float4*)(A + (size_t)gr * HH + kb + a_c)
                             : make_float4(0.f, 0.f, 0.f, 0.f);
            b_tmp = *(const float4*)(W + (size_t)(kb + b_r) * HH + col0 + b_c);
        }
        #pragma unroll
        for (int kk = 0; kk < BK; ++kk) {
            float4 a0 = *(const float4*)&As[cur][kk][ty * 4];
            float4 a1 = *(const float4*)&As[cur][kk][64 + ty * 4];
            float4 b0 = *(const float4*)&Bs[cur][kk][tx * 4];
            float4 b1 = *(const float4*)&Bs[cur][kk][64 + tx * 4];
            float ar[8] = {a0.x, a0.y, a0.z, a0.w, a1.x, a1.y, a1.z, a1.w};
            float br[8] = {b0.x, b0.y, b0.z, b0.w, b1.x, b1.y, b1.z, b1.w};
            #pragma unroll
            for (int i = 0; i < 8; ++i)
                #pragma unroll
                for (int j = 0; j < 8; ++j)
                    acc[i][j] += ar[i] * br[j];
        }
        if (kt + 1 < NT) {
            const int nxt = cur ^ 1;
            As[nxt][a_c + 0][a_r] = a_tmp.x;
            As[nxt][a_c + 1][a_r] = a_tmp.y;
            As[nxt][a_c + 2][a_r] = a_tmp.z;
            As[nxt][a_c + 3][a_r] = a_tmp.w;
            *(float4*)&Bs[nxt][b_r][b_c] = b_tmp;
        }
        __syncthreads();
    }

    // epilogue
    #pragma unroll
    for (int ih = 0; ih < 2; ++ih) {
        #pragma unroll
        for (int i = 0; i < 4; ++i) {
            const int r = row0 + ih * 64 + ty * 4 + i;
            if (r >= M) continue;
            #pragma unroll
            for (int jh = 0; jh < 2; ++jh) {
                const int cb = col0 + jh * 64 + tx * 4;
                float vals[4];
                #pragma unroll
                for (int e = 0; e < 4; ++e) {
                    float vv = acc[ih * 4 + i][jh * 4 + e] + bias[cb + e];
                    if (EPI == 1) vv += pos[(size_t)(r & (LL - 1)) * HH + cb + e];
                    if (EPI == 2) vv = (vv > 0.f) ? vv : 0.2f * vv;
                    vals[e] = vv;
                }
                *(float4*)(C + (size_t)r * HH + cb) =
                    make_float4(vals[0], vals[1], vals[2], vals[3]);
            }
        }
    }
}

// generic GEMM kernel: A either a harness input (AID==-1 -> Aparam) or scratch
template<int EPI, int AID, int DID>
__global__ __launch_bounds__(256)
void sgemm_kernel(const float* __restrict__ Aparam, const float* __restrict__ W,
                  int M, const float* __restrict__ bias, const float* __restrict__ pos)
{
    const float* A = (AID == BUF_PARAM) ? Aparam : sbuf<AID>();
    sgemm_body<EPI>(A, W, sbuf<DID>(), M, bias, pos);
}

// fused Q/K/V projection: blockIdx.z in {0,1,2} selects weight/bias/output
__global__ __launch_bounds__(256)
void qkv_gemm_kernel(const float* __restrict__ wq, const float* __restrict__ wk,
                     const float* __restrict__ wv, const float* __restrict__ bq,
                     const float* __restrict__ bk, const float* __restrict__ bv,
                     int M)
{
    const int z = blockIdx.z;
    const float* W    = (z == 0) ? wq : (z == 1) ? wk : wv;
    const float* bias = (z == 0) ? bq : (z == 1) ? bk : bv;
    float* C          = (z == 0) ? g_q : (z == 1) ? g_k : g_v;
    sgemm_body<0>(g_xy, W, C, M, bias, nullptr);
}

// ------------------------- relay init (column mean) -------------------------
__global__ void colmean_partial()
{
    const int b = blockIdx.x, chunk = blockIdx.y, c = threadIdx.x;
    float s = 0.f;
    const int l0 = chunk * 128;
    for (int l = l0; l < l0 + 128; ++l)
        s += g_nodes[((size_t)b * LL + l) * HH + c];
    g_part[(b * 16 + chunk) * HH + c] = s;
}

__global__ void colmean_final()
{
    const int b = blockIdx.x, c = threadIdx.x;
    float s = 0.f;
    for (int t = 0; t < 16; ++t) s += g_part[(b * 16 + t) * HH + c];
    g_relay[b * HH + c] = s * (1.0f / (float)LL);
}

// ------------------------- LayerNorm + concat relay -------------------------
__global__ void ln_concat_kernel(const float* __restrict__ gam, const float* __restrict__ bet)
{
    const int row = blockIdx.x;          // 0 .. B*2049-1
    const int b = row / LP1, l = row % LP1;
    const int tid = threadIdx.x;         // 128 threads, 4 floats each
    float* out = g_xy + (size_t)row * HH;

    if (l == LL) {   // relay row, raw copy
        *(float4*)(out + tid * 4) = *(const float4*)(g_relay + b * HH + tid * 4);
        return;
    }
    const float* x = g_nodes + ((size_t)b * LL + l) * HH;
    float4 vv = *(const float4*)(x + tid * 4);
    float s  = vv.x + vv.y + vv.z + vv.w;
    float s2 = vv.x * vv.x + vv.y * vv.y + vv.z * vv.z + vv.w * vv.w;

    #pragma unroll
    for (int o = 16; o > 0; o >>= 1) {
        s  += __shfl_xor_sync(0xffffffffu, s,  o);
        s2 += __shfl_xor_sync(0xffffffffu, s2, o);
    }
    __shared__ float sh[8];
    const int wid = tid >> 5;
    if ((tid & 31) == 0) { sh[wid] = s; sh[4 + wid] = s2; }
    __syncthreads();
    const float S  = sh[0] + sh[1] + sh[2] + sh[3];
    const float S2 = sh[4] + sh[5] + sh[6] + sh[7];
    const float mu  = S * (1.0f / (float)HH);
    const float var = S2 * (1.0f / (float)HH) - mu * mu;
    const float inv = rsqrtf(var + 1e-6f);

    float4 g4 = *(const float4*)(gam + tid * 4);
    float4 b4 = *(const float4*)(bet + tid * 4);
    float4 o4;
    o4.x = (vv.x - mu) * inv * g4.x + b4.x;
    o4.y = (vv.y - mu) * inv * g4.y + b4.y;
    o4.z = (vv.z - mu) * inv * g4.z + b4.z;
    o4.w = (vv.w - mu) * inv * g4.w + b4.w;
    *(float4*)(out + tid * 4) = o4;
}

// -------------------- ring (windowed) attention: 1 warp / (b,l,h) -----------
__global__ void ring_attn_kernel()
{
    const int lane = threadIdx.x & 31;
    const int gw = blockIdx.x * (blockDim.x >> 5) + (threadIdx.x >> 5);
    const int h = gw & 7;
    const int l = (gw >> 3) & (LL - 1);
    const int b = gw >> 14;

    const int qoff = (b * LP1 + l) * HH + h * HD;
    const float q0 = g_q[qoff + lane];
    const float q1 = g_q[qoff + 32 + lane];

    float s[4];
    int   koff[4];
    bool  ok[4];
    #pragma unroll
    for (int w = 0; w < 3; ++w) {
        const int lp = l - 1 + w;
        ok[w]   = (lp >= 0) && (lp < LL);
        koff[w] = (b * LP1 + lp) * HH + h * HD;
    }
    ok[3]   = true;
    koff[3] = (b * LP1 + LL) * HH + h * HD;   // relay row

    #pragma unroll
    for (int w = 0; w < 4; ++w) {
        float p = 0.f;
        if (ok[w]) p = q0 * g_k[koff[w] + lane] + q1 * g_k[koff[w] + 32 + lane];
        s[w] = p;
    }
    #pragma unroll
    for (int o = 16; o > 0; o >>= 1) {
        #pragma unroll
        for (int w = 0; w < 4; ++w)
            s[w] += __shfl_xor_sync(0xffffffffu, s[w], o);
    }
    const float scale = 0.125f;   // 1/sqrt(64)
    #pragma unroll
    for (int w = 0; w < 4; ++w) s[w] *= scale;   // pad positions stay exactly 0
    float m = fmaxf(fmaxf(s[0], s[1]), fmaxf(s[2], s[3]));
    float e[4], sum = 0.f;
    #pragma unroll
    for (int w = 0; w < 4; ++w) { e[w] = expf(s[w] - m); sum += e[w]; }
    const float inv = 1.0f / sum;

    float a0 = 0.f, a1 = 0.f;
    #pragma unroll
    for (int w = 0; w < 4; ++w) {
        if (ok[w]) {
            const float al = e[w] * inv;
            a0 += al * g_v[koff[w] + lane];
            a1 += al * g_v[koff[w] + 32 + lane];
        }
    }
    const int aoff = (b * LL + l) * HH + h * HD;
    g_att[aoff + lane]      = a0;
    g_att[aoff + 32 + lane] = a1;
}

// --------------- star (relay) attention: 1 block / (b,h), 256 thr -----------
__global__ void star_attn_kernel()
{
    const int b = blockIdx.x >> 3, h = blockIdx.x & 7;
    const int tid = threadIdx.x;   // 256

    __shared__ float sc[LP1];
    __shared__ float qs[HD];
    __shared__ float red[8];
    __shared__ float part[4][HD];
    __shared__ float s_m, s_inv;

    const int qrow = (b * LP1 + LL) * HH + h * HD;
    if (tid < HD) qs[tid] = g_q[qrow + tid];
    __syncthreads();

    for (int j = tid; j < LP1; j += 256) {
        const float* kp = g_k + ((size_t)(b * LP1 + j)) * HH + h * HD;
        float s = 0.f;
        #pragma unroll
        for (int d = 0; d < HD; ++d) s += qs[d] * kp[d];
        sc[j] = s * 0.125f;
    }
    __syncthreads();

    // block max
    float m = -3.4e38f;
    for (int j = tid; j < LP1; j += 256) m = fmaxf(m, sc[j]);
    #pragma unroll
    for (int o = 16; o > 0; o >>= 1) m = fmaxf(m, __shfl_xor_sync(0xffffffffu, m, o));
    if ((tid & 31) == 0) red[tid >> 5] = m;
    __syncthreads();
    if (tid == 0) {
        float mm = red[0];
        for (int w = 1; w < 8; ++w) mm = fmaxf(mm, red[w]);
        s_m = mm;
    }
    __syncthreads();
    m = s_m;

    // exp + sum
    float sum = 0.f;
    for (int j = tid; j < LP1; j += 256) {
        const float e = expf(sc[j] - m);
        sc[j] = e;
        sum += e;
    }
    #pragma unroll
    for (int o = 16; o > 0; o >>= 1) sum += __shfl_xor_sync(0xffffffffu, sum, o);
    __syncthreads();            // protect red[] reuse
    if ((tid & 31) == 0) red[tid >> 5] = sum;
    __syncthreads();
    if (tid == 0) {
        float ss = 0.f;
        for (int w = 0; w < 8; ++w) ss += red[w];
        s_inv = 1.0f / ss;
    }
    __syncthreads();
    const float inv = s_inv;

    // weighted V accumulation: 4 j-groups x 64 d-lanes
    const int g = tid >> 6, d = tid & 63;
    float acc = 0.f;
    for (int j = g; j < LP1; j += 4)
        acc += sc[j] * g_v[((size_t)(b * LP1 + j)) * HH + h * HD + d];
    part[g][d] = acc;
    __syncthreads();
    if (tid < HD) {
        const float r = (part[0][tid] + part[1][tid] + part[2][tid] + part[3][tid]) * inv;
        g_attr[b * HH + h * HD + tid] = r;
    }
}

// ------------------- star output projection (tiny GEMM) ---------------------
__global__ void star_out_kernel(const float* __restrict__ wo, const float* __restrict__ bo)
{
    const int b = blockIdx.x, c = threadIdx.x;   // 512 threads
    __shared__ float a[HH];
    a[c] = g_attr[b * HH + c];
    __syncthreads();
    float s = bo[c];
    #pragma unroll 8
    for (int d = 0; d < HH; ++d) s += a[d] * wo[d * HH + c];
    g_relay[b * HH + c] = (s > 0.f) ? s : 0.2f * s;
}

// -------------------------- final: max + combine ----------------------------
__global__ void maxred_partial()
{
    const int b = blockIdx.x, chunk = blockIdx.y, c = threadIdx.x;
    float m = -3.4e38f;
    const int l0 = chunk * 128;
    for (int l = l0; l < l0 + 128; ++l)
        m = fmaxf(m, g_nodes[((size_t)b * LL + l) * HH + c]);
    g_part[(b * 16 + chunk) * HH + c] = m;
}

__global__ void final_out_kernel(float* __restrict__ out)
{
    const int b = blockIdx.x, c = threadIdx.x;
    float m = -3.4e38f;
    for (int t = 0; t < 16; ++t) m = fmaxf(m, g_part[(b * 16 + t) * HH + c]);
    out[b * HH + c] = 0.5f * (g_relay[b * HH + c] + m);
}

// ------------------------------- host driver --------------------------------
extern "C" void kernel_launch(void* const* d_in, const int* in_sizes, int n_in,
                              void* d_out, int out_size)
{
    const float* data    = (const float*)d_in[0];
    const float* fc_w    = (const float*)d_in[1];
    const float* fc_b    = (const float*)d_in[2];
    const float* pos_emb = (const float*)d_in[3];
    const float* ln_g    = (const float*)d_in[4];
    const float* ln_b    = (const float*)d_in[5];
    const float* wq      = (const float*)d_in[6];
    const float* wk      = (const float*)d_in[7];
    const float* wv      = (const float*)d_in[8];
    const float* bq      = (const float*)d_in[9];
    const float* bk      = (const float*)d_in[10];
    const float* bv      = (const float*)d_in[11];
    const float* ring_wo = (const float*)d_in[12];
    const float* ring_bo = (const float*)d_in[13];
    const float* star_wo = (const float*)d_in[14];
    const float* star_bo = (const float*)d_in[15];
    float* out = (float*)d_out;

    const int M_full = BB * LL;    // 16384
    const int M_xy   = BB * LP1;   // 16392
    const dim3 gFull(HH / BN, (M_full + BM - 1) / BM);      // (4,128)
    const dim3 gXY  (HH / BN, (M_xy   + BM - 1) / BM);      // (4,129)
    const dim3 gQKV (HH / BN, (M_xy   + BM - 1) / BM, 3);   // (4,129,3)

    // embedding: nodes = data @ fc_w + fc_b + pos_emb
    sgemm_kernel<1, BUF_PARAM, BUF_NODES><<<gFull, 256>>>(data, fc_w, M_full, fc_b, pos_emb);

    // relay = mean_l(embs)
    colmean_partial<<<dim3(BB, 16), HH>>>();
    colmean_final<<<BB, HH>>>();

    for (int i = 0; i < NL; ++i) {
        const int wOff = i * HH * HH;
        const int bOff = i * HH;

        ln_concat_kernel<<<M_xy, 128>>>(ln_g + bOff, ln_b + bOff);

        qkv_gemm_kernel<<<gQKV, 256>>>(wq + wOff, wk + wOff, wv + wOff,
                                       bq + bOff, bk + bOff, bv + bOff, M_xy);

        ring_attn_kernel<<<(BB * LL * NHD) / 8, 256>>>();

        sgemm_kernel<2, BUF_ATT, BUF_NODES><<<gFull, 256>>>(nullptr, ring_wo + wOff,
                                                            M_full, ring_bo + bOff, nullptr);

        star_attn_kernel<<<BB * NHD, 256>>>();
        star_out_kernel<<<BB, HH>>>(star_wo + wOff, star_bo + bOff);
    }

    maxred_partial<<<dim3(BB, 16), HH>>>();
    final_out_kernel<<<BB, HH>>>(out);
}

// round 4
// speedup vs baseline: 1.6902x; 1.6902x over previous
#include <cuda_runtime.h>
#include <cuda_bf16.h>
#include <math.h>
#include <stdint.h>

// ---------------------------------------------------------------------------
// StarTransformer: B=8, L=2048, H=512, NH=8, HD=64, NUM_LAYERS=4
// GEMMs via mma.sync bf16 (HMMA), 3-term split-bf16 for fp32-like accuracy
// ---------------------------------------------------------------------------
#define BB   8
#define LL   2048
#define LP1  2049
#define HH   512
#define NHD  8
#define HD   64
#define NL   4
#define NSLOT 17        // fc_w + 4 layers x (wq,wk,wv,ring_wo)

// -------------------- scratch (device globals, no allocs) -------------------
__device__ float g_nodes[BB * LL * HH];
__device__ float g_q   [BB * LP1 * HH];
__device__ float g_k   [BB * LP1 * HH];
__device__ float g_v   [BB * LP1 * HH];
__device__ float g_relay[BB * HH];
__device__ float g_attr [BB * HH];
__device__ float g_part [BB * 16 * HH];

__device__ __nv_bfloat16 g_data_h[BB * LL * HH];
__device__ __nv_bfloat16 g_data_l[BB * LL * HH];
__device__ __nv_bfloat16 g_xy_h  [BB * LP1 * HH];
__device__ __nv_bfloat16 g_xy_l  [BB * LP1 * HH];
__device__ __nv_bfloat16 g_att_h [BB * LL * HH];
__device__ __nv_bfloat16 g_att_l [BB * LL * HH];
__device__ __nv_bfloat16 g_wt_h  [NSLOT * HH * HH];   // W^T [n][k], bf16 hi
__device__ __nv_bfloat16 g_wt_l  [NSLOT * HH * HH];   // W^T [n][k], bf16 lo

// ------------------------------ helpers -------------------------------------
__device__ __forceinline__ uint32_t smem_u32(const void* p) {
    uint32_t a;
    asm("{ .reg .u64 t; cvta.to.shared.u64 t, %1; cvt.u32.u64 %0, t; }"
        : "=r"(a) : "l"(p));
    return a;
}
__device__ __forceinline__ void cp_async16(uint32_t dst, const void* src, uint32_t sz) {
    asm volatile("cp.async.cg.shared.global [%0], [%1], 16, %2;"
                 :: "r"(dst), "l"(src), "r"(sz));
}
#define CP_COMMIT() asm volatile("cp.async.commit_group;" ::: "memory")
#define CP_WAIT(n)  asm volatile("cp.async.wait_group %0;" :: "n"(n) : "memory")

__device__ __forceinline__ void mma16816(float* c, const uint32_t* a, const uint32_t* b) {
    asm volatile(
        "mma.sync.aligned.m16n8k16.row.col.f32.bf16.bf16.f32 "
        "{%0,%1,%2,%3}, {%4,%5,%6,%7}, {%8,%9}, {%0,%1,%2,%3};"
        : "+f"(c[0]), "+f"(c[1]), "+f"(c[2]), "+f"(c[3])
        : "r"(a[0]), "r"(a[1]), "r"(a[2]), "r"(a[3]), "r"(b[0]), "r"(b[1]));
}

__device__ __forceinline__ void split_bf16(float x, __nv_bfloat16& h, __nv_bfloat16& l) {
    h = __float2bfloat16_rn(x);
    l = __float2bfloat16_rn(x - __bfloat162float(h));
}

// ------------------------ mma.sync GEMM kernel ------------------------------
// D[M x 512] = A[M x 512] @ W_slot^T + epilogue. Tile 128x128, BK=32.
// 8 warps as 2(m) x 4(n): warp tile 64m x 32n; frags 4m x 4n of m16n8k16.
// 3-term split: Ah*Bh + Ah*Bl + Al*Bh into one f32 accumulator.
// MODE 0: emb  (A = data_h/l, C = nodes, EPI: +bias +pos)
// MODE 1: qkv  (A = xy_h/l, blockIdx.z -> q/k/v, EPI: +bias)
// MODE 2: ring (A = att_h/l, C = nodes, EPI: leaky_relu(+bias))
#define PADK 40                      // bf16 elems per smem row (32 + 8 pad)
#define SUB_B  (128 * PADK * 2)      // 10240 bytes per subtile
#define STAGE_B (4 * SUB_B)          // Ah, Al, Bh, Bl
#define GEMM_SMEM (2 * STAGE_B)      // 81920 bytes

template<int MODE>
__global__ __launch_bounds__(256, 1)
void mma_gemm(int layer, int M,
              const float* __restrict__ b0, const float* __restrict__ b1,
              const float* __restrict__ b2, const float* __restrict__ pos)
{
    extern __shared__ __align__(16) char smem[];
    const uint32_t sb = smem_u32(smem);
    const int tid = threadIdx.x;
    const int lane = tid & 31, wid = tid >> 5;
    const int row0 = blockIdx.y * 128;
    const int col0 = blockIdx.x * 128;

    const __nv_bfloat16 *a_h, *a_l;
    float* C;
    const float* bias;
    int slot;
    if (MODE == 0) { a_h = g_data_h; a_l = g_data_l; C = g_nodes; bias = b0; slot = 0; }
    else if (MODE == 1) {
        const int z = blockIdx.z;
        a_h = g_xy_h; a_l = g_xy_l;
        C    = (z == 0) ? g_q : (z == 1) ? g_k : g_v;
        bias = (z == 0) ? b0  : (z == 1) ? b1  : b2;
        slot = 1 + layer * 4 + z;
    } else { a_h = g_att_h; a_l = g_att_l; C = g_nodes; bias = b0; slot = 1 + layer * 4 + 3; }
    const __nv_bfloat16* w_h = g_wt_h + (size_t)slot * HH * HH;
    const __nv_bfloat16* w_l = g_wt_l + (size_t)slot * HH * HH;

    // loader mapping: per subtile 512 x 16B words; thread does words tid, tid+256
    const int w0r = tid >> 2, w0c = (tid & 3) * 8;          // word tid
    const int w1r = (tid + 256) >> 2, w1c = ((tid + 256) & 3) * 8;

    auto load_stage = [&](int stage, int kc) {
        const uint32_t stb = sb + stage * STAGE_B;
        #pragma unroll
        for (int sub = 0; sub < 4; ++sub) {
            const __nv_bfloat16* base =
                (sub == 0) ? a_h : (sub == 1) ? a_l : (sub == 2) ? w_h : w_l;
            #pragma unroll
            for (int half = 0; half < 2; ++half) {
                const int row = half ? w1r : w0r;
                const int col = half ? w1c : w0c;
                uint32_t sz = 16;
                const __nv_bfloat16* src;
                if (sub < 2) {
                    const int gr = row0 + row;
                    src = base + (size_t)gr * HH + kc + col;
                    if (gr >= M) { sz = 0; src = base; }
                } else {
                    src = base + (size_t)(col0 + row) * HH + kc + col;
                }
                cp_async16(stb + sub * SUB_B + (row * PADK + col) * 2, src, sz);
            }
        }
        CP_COMMIT();
    };

    // warp tiling
    const int wm = (wid >> 2) * 64;     // 0 or 64
    const int wn = (wid & 3) * 32;      // 0,32,64,96

    float acc[4][4][4];
    #pragma unroll
    for (int mf = 0; mf < 4; ++mf)
        #pragma unroll
        for (int nf = 0; nf < 4; ++nf)
            #pragma unroll
            for (int e = 0; e < 4; ++e) acc[mf][nf][e] = 0.f;

    load_stage(0, 0);

    const int NT = HH / 32;   // 16
    for (int kt = 0; kt < NT; ++kt) {
        if (kt + 1 < NT) load_stage((kt + 1) & 1, (kt + 1) * 32);
        if (kt + 1 < NT) { CP_WAIT(1); } else { CP_WAIT(0); }
        __syncthreads();

        const char* stb = smem + (kt & 1) * STAGE_B;
        const __nv_bfloat16* sAh = (const __nv_bfloat16*)(stb);
        const __nv_bfloat16* sAl = (const __nv_bfloat16*)(stb + SUB_B);
        const __nv_bfloat16* sBh = (const __nv_bfloat16*)(stb + 2 * SUB_B);
        const __nv_bfloat16* sBl = (const __nv_bfloat16*)(stb + 3 * SUB_B);

        #pragma unroll
        for (int ks = 0; ks < 2; ++ks) {
            const int k0 = ks * 16 + (lane & 3) * 2;
            uint32_t ah[4][4], al[4][4], bh[4][2], bl[4][2];
            #pragma unroll
            for (int mf = 0; mf < 4; ++mf) {
                const int r = wm + mf * 16 + (lane >> 2);
                ah[mf][0] = *(const uint32_t*)&sAh[r * PADK + k0];
                ah[mf][1] = *(const uint32_t*)&sAh[(r + 8) * PADK + k0];
                ah[mf][2] = *(const uint32_t*)&sAh[r * PADK + k0 + 8];
                ah[mf][3] = *(const uint32_t*)&sAh[(r + 8) * PADK + k0 + 8];
                al[mf][0] = *(const uint32_t*)&sAl[r * PADK + k0];
                al[mf][1] = *(const uint32_t*)&sAl[(r + 8) * PADK + k0];
                al[mf][2] = *(const uint32_t*)&sAl[r * PADK + k0 + 8];
                al[mf][3] = *(const uint32_t*)&sAl[(r + 8) * PADK + k0 + 8];
            }
            #pragma unroll
            for (int nf = 0; nf < 4; ++nf) {
                const int n = wn + nf * 8 + (lane >> 2);
                bh[nf][0] = *(const uint32_t*)&sBh[n * PADK + k0];
                bh[nf][1] = *(const uint32_t*)&sBh[n * PADK + k0 + 8];
                bl[nf][0] = *(const uint32_t*)&sBl[n * PADK + k0];
                bl[nf][1] = *(const uint32_t*)&sBl[n * PADK + k0 + 8];
            }
            #pragma unroll
            for (int mf = 0; mf < 4; ++mf)
                #pragma unroll
                for (int nf = 0; nf < 4; ++nf) {
                    mma16816(acc[mf][nf], ah[mf], bh[nf]);
                    mma16816(acc[mf][nf], ah[mf], bl[nf]);
                    mma16816(acc[mf][nf], al[mf], bh[nf]);
                }
        }
        __syncthreads();
    }

    // epilogue
    #pragma unroll
    for (int mf = 0; mf < 4; ++mf) {
        const int rlo = row0 + wm + mf * 16 + (lane >> 2);
        #pragma unroll
        for (int nf = 0; nf < 4; ++nf) {
            const int c = col0 + wn + nf * 8 + (lane & 3) * 2;
            const float bx = bias[c], by = bias[c + 1];
            #pragma unroll
            for (int hrow = 0; hrow < 2; ++hrow) {
                const int r = rlo + hrow * 8;
                if (r >= M) continue;
                float vx = acc[mf][nf][hrow * 2 + 0] + bx;
                float vy = acc[mf][nf][hrow * 2 + 1] + by;
                if (MODE == 0) {
                    const size_t po = (size_t)(r & (LL - 1)) * HH + c;
                    vx += pos[po];
                    vy += pos[po + 1];
                }
                if (MODE == 2) {
                    vx = (vx > 0.f) ? vx : 0.2f * vx;
                    vy = (vy > 0.f) ? vy : 0.2f * vy;
                }
                *(float2*)(C + (size_t)r * HH + c) = make_float2(vx, vy);
            }
        }
    }
}

// ------------------- weight transpose + bf16 hi/lo split --------------------
__global__ void wconv_kernel(const float* __restrict__ fc_w, const float* __restrict__ wq,
                             const float* __restrict__ wk, const float* __restrict__ wv,
                             const float* __restrict__ ring_wo)
{
    const int z = blockIdx.z;
    const float* W;
    if (z == 0) W = fc_w;
    else {
        const int s = z - 1, layer = s >> 2, which = s & 3;
        const float* base = (which == 0) ? wq : (which == 1) ? wk
                          : (which == 2) ? wv : ring_wo;
        W = base + (size_t)layer * HH * HH;
    }
    __shared__ float t[32][33];
    const int x0 = blockIdx.x * 32, y0 = blockIdx.y * 32;
    const int tx = threadIdx.x, ty = threadIdx.y;   // (32,8)
    #pragma unroll
    for (int i = 0; i < 4; ++i)
        t[ty * 4 + i][tx] = W[(size_t)(y0 + ty * 4 + i) * HH + x0 + tx];
    __syncthreads();
    __nv_bfloat16* wh = g_wt_h + (size_t)z * HH * HH;
    __nv_bfloat16* wl = g_wt_l + (size_t)z * HH * HH;
    #pragma unroll
    for (int i = 0; i < 4; ++i) {
        const int n = x0 + ty * 4 + i, k = y0 + tx;
        __nv_bfloat16 h, l;
        split_bf16(t[tx][ty * 4 + i], h, l);
        wh[(size_t)n * HH + k] = h;
        wl[(size_t)n * HH + k] = l;
    }
}

// ----------------------- data -> bf16 hi/lo conversion ----------------------
__global__ void aconv_kernel(const float* __restrict__ x)
{
    const int n4 = BB * LL * HH / 4;
    for (int i = blockIdx.x * blockDim.x + threadIdx.x; i < n4;
         i += gridDim.x * blockDim.x) {
        const float4 v = *(const float4*)(x + (size_t)i * 4);
        __nv_bfloat16 h[4], l[4];
        split_bf16(v.x, h[0], l[0]); split_bf16(v.y, h[1], l[1]);
        split_bf16(v.z, h[2], l[2]); split_bf16(v.w, h[3], l[3]);
        *(uint2*)(g_data_h + (size_t)i * 4) = *(uint2*)h;
        *(uint2*)(g_data_l + (size_t)i * 4) = *(uint2*)l;
    }
}

// ------------------------- relay init (column mean) -------------------------
__global__ void colmean_partial()
{
    const int b = blockIdx.x, chunk = blockIdx.y, c = threadIdx.x;
    float s = 0.f;
    const int l0 = chunk * 128;
    for (int l = l0; l < l0 + 128; ++l)
        s += g_nodes[((size_t)b * LL + l) * HH + c];
    g_part[(b * 16 + chunk) * HH + c] = s;
}
__global__ void colmean_final()
{
    const int b = blockIdx.x, c = threadIdx.x;
    float s = 0.f;
    for (int t = 0; t < 16; ++t) s += g_part[(b * 16 + t) * HH + c];
    g_relay[b * HH + c] = s * (1.0f / (float)LL);
}

// ---------------- LayerNorm + concat relay -> bf16 hi/lo --------------------
__global__ void ln_concat_kernel(const float* __restrict__ gam, const float* __restrict__ bet)
{
    const int row = blockIdx.x;          // 0 .. B*2049-1
    const int b = row / LP1, l = row % LP1;
    const int tid = threadIdx.x;         // 128 threads, 4 floats each
    __nv_bfloat16* oh = g_xy_h + (size_t)row * HH + tid * 4;
    __nv_bfloat16* ol = g_xy_l + (size_t)row * HH + tid * 4;

    float4 vv;
    if (l == LL) {
        vv = *(const float4*)(g_relay + b * HH + tid * 4);
        __nv_bfloat16 h[4], q[4];
        split_bf16(vv.x, h[0], q[0]); split_bf16(vv.y, h[1], q[1]);
        split_bf16(vv.z, h[2], q[2]); split_bf16(vv.w, h[3], q[3]);
        *(uint2*)oh = *(uint2*)h;
        *(uint2*)ol = *(uint2*)q;
        return;
    }
    const float* x = g_nodes + ((size_t)b * LL + l) * HH;
    vv = *(const float4*)(x + tid * 4);
    float s  = vv.x + vv.y + vv.z + vv.w;
    float s2 = vv.x * vv.x + vv.y * vv.y + vv.z * vv.z + vv.w * vv.w;
    #pragma unroll
    for (int o = 16; o > 0; o >>= 1) {
        s  += __shfl_xor_sync(0xffffffffu, s,  o);
        s2 += __shfl_xor_sync(0xffffffffu, s2, o);
    }
    __shared__ float sh[8];
    const int wid = tid >> 5;
    if ((tid & 31) == 0) { sh[wid] = s; sh[4 + wid] = s2; }
    __syncthreads();
    const float S  = sh[0] + sh[1] + sh[2] + sh[3];
    const float S2 = sh[4] + sh[5] + sh[6] + sh[7];
    const float mu  = S * (1.0f / (float)HH);
    const float var = S2 * (1.0f / (float)HH) - mu * mu;
    const float inv = rsqrtf(var + 1e-6f);

    const float4 g4 = *(const float4*)(gam + tid * 4);
    const float4 b4 = *(const float4*)(bet + tid * 4);
    float o0 = (vv.x - mu) * inv * g4.x + b4.x;
    float o1 = (vv.y - mu) * inv * g4.y + b4.y;
    float o2 = (vv.z - mu) * inv * g4.z + b4.z;
    float o3 = (vv.w - mu) * inv * g4.w + b4.w;
    __nv_bfloat16 h[4], q[4];
    split_bf16(o0, h[0], q[0]); split_bf16(o1, h[1], q[1]);
    split_bf16(o2, h[2], q[2]); split_bf16(o3, h[3], q[3]);
    *(uint2*)oh = *(uint2*)h;
    *(uint2*)ol = *(uint2*)q;
}

// -------------------- ring attention: 1 warp / (b,l,h) ----------------------
__global__ void ring_attn_kernel()
{
    const int lane = threadIdx.x & 31;
    const int gw = blockIdx.x * (blockDim.x >> 5) + (threadIdx.x >> 5);
    const int h = gw & 7;
    const int l = (gw >> 3) & (LL - 1);
    const int b = gw >> 14;

    const int qoff = (b * LP1 + l) * HH + h * HD;
    const float q0 = g_q[qoff + lane];
    const float q1 = g_q[qoff + 32 + lane];

    float s[4];
    int   koff[4];
    bool  ok[4];
    #pragma unroll
    for (int w = 0; w < 3; ++w) {
        const int lp = l - 1 + w;
        ok[w]   = (lp >= 0) && (lp < LL);
        koff[w] = (b * LP1 + lp) * HH + h * HD;
    }
    ok[3]   = true;
    koff[3] = (b * LP1 + LL) * HH + h * HD;

    #pragma unroll
    for (int w = 0; w < 4; ++w) {
        float p = 0.f;
        if (ok[w]) p = q0 * g_k[koff[w] + lane] + q1 * g_k[koff[w] + 32 + lane];
        s[w] = p;
    }
    #pragma unroll
    for (int o = 16; o > 0; o >>= 1) {
        #pragma unroll
        for (int w = 0; w < 4; ++w)
            s[w] += __shfl_xor_sync(0xffffffffu, s[w], o);
    }
    #pragma unroll
    for (int w = 0; w < 4; ++w) s[w] *= 0.125f;
    float m = fmaxf(fmaxf(s[0], s[1]), fmaxf(s[2], s[3]));
    float e[4], sum = 0.f;
    #pragma unroll
    for (int w = 0; w < 4; ++w) { e[w] = expf(s[w] - m); sum += e[w]; }
    const float inv = 1.0f / sum;

    float a0 = 0.f, a1 = 0.f;
    #pragma unroll
    for (int w = 0; w < 4; ++w) {
        if (ok[w]) {
            const float al = e[w] * inv;
            a0 += al * g_v[koff[w] + lane];
            a1 += al * g_v[koff[w] + 32 + lane];
        }
    }
    const int aoff = (b * LL + l) * HH + h * HD;
    __nv_bfloat16 h0, l0, h1, l1;
    split_bf16(a0, h0, l0);
    split_bf16(a1, h1, l1);
    g_att_h[aoff + lane]      = h0;
    g_att_l[aoff + lane]      = l0;
    g_att_h[aoff + 32 + lane] = h1;
    g_att_l[aoff + 32 + lane] = l1;
}

// --------------- star attention: 1 block / (b,h), 256 thr -------------------
__global__ void star_attn_kernel()
{
    const int b = blockIdx.x >> 3, h = blockIdx.x & 7;
    const int tid = threadIdx.x;

    __shared__ float sc[LP1];
    __shared__ float qs[HD];
    __shared__ float red[8];
    __shared__ float part[4][HD];
    __shared__ float s_m, s_inv;

    const int qrow = (b * LP1 + LL) * HH + h * HD;
    if (tid < HD) qs[tid] = g_q[qrow + tid];
    __syncthreads();

    for (int j = tid; j < LP1; j += 256) {
        const float* kp = g_k + ((size_t)(b * LP1 + j)) * HH + h * HD;
        float s = 0.f;
        #pragma unroll
        for (int d = 0; d < HD; ++d) s += qs[d] * kp[d];
        sc[j] = s * 0.125f;
    }
    __syncthreads();

    float m = -3.4e38f;
    for (int j = tid; j < LP1; j += 256) m = fmaxf(m, sc[j]);
    #pragma unroll
    for (int o = 16; o > 0; o >>= 1) m = fmaxf(m, __shfl_xor_sync(0xffffffffu, m, o));
    if ((tid & 31) == 0) red[tid >> 5] = m;
    __syncthreads();
    if (tid == 0) {
        float mm = red[0];
        for (int w = 1; w < 8; ++w) mm = fmaxf(mm, red[w]);
        s_m = mm;
    }
    __syncthreads();
    m = s_m;

    float sum = 0.f;
    for (int j = tid; j < LP1; j += 256) {
        const float e = expf(sc[j] - m);
        sc[j] = e;
        sum += e;
    }
    #pragma unroll
    for (int o = 16; o > 0; o >>= 1) sum += __shfl_xor_sync(0xffffffffu, sum, o);
    __syncthreads();
    if ((tid & 31) == 0) red[tid >> 5] = sum;
    __syncthreads();
    if (tid == 0) {
        float ss = 0.f;
        for (int w = 0; w < 8; ++w) ss += red[w];
        s_inv = 1.0f / ss;
    }
    __syncthreads();
    const float inv = s_inv;

    const int g = tid >> 6, d = tid & 63;
    float acc = 0.f;
    for (int j = g; j < LP1; j += 4)
        acc += sc[j] * g_v[((size_t)(b * LP1 + j)) * HH + h * HD + d];
    part[g][d] = acc;
    __syncthreads();
    if (tid < HD) {
        const float r = (part[0][tid] + part[1][tid] + part[2][tid] + part[3][tid]) * inv;
        g_attr[b * HH + h * HD + tid] = r;
    }
}

// ------------------- star output projection (tiny GEMM) ---------------------
__global__ void star_out_kernel(const float* __restrict__ wo, const float* __restrict__ bo)
{
    const int b = blockIdx.x, c = threadIdx.x;
    __shared__ float a[HH];
    a[c] = g_attr[b * HH + c];
    __syncthreads();
    float s = bo[c];
    #pragma unroll 8
    for (int d = 0; d < HH; ++d) s += a[d] * wo[d * HH + c];
    g_relay[b * HH + c] = (s > 0.f) ? s : 0.2f * s;
}

// -------------------------- final: max + combine ----------------------------
__global__ void maxred_partial()
{
    const int b = blockIdx.x, chunk = blockIdx.y, c = threadIdx.x;
    float m = -3.4e38f;
    const int l0 = chunk * 128;
    for (int l = l0; l < l0 + 128; ++l)
        m = fmaxf(m, g_nodes[((size_t)b * LL + l) * HH + c]);
    g_part[(b * 16 + chunk) * HH + c] = m;
}
__global__ void final_out_kernel(float* __restrict__ out)
{
    const int b = blockIdx.x, c = threadIdx.x;
    float m = -3.4e38f;
    for (int t = 0; t < 16; ++t) m = fmaxf(m, g_part[(b * 16 + t) * HH + c]);
    out[b * HH + c] = 0.5f * (g_relay[b * HH + c] + m);
}

// ------------------------------- host driver --------------------------------
extern "C" void kernel_launch(void* const* d_in, const int* in_sizes, int n_in,
                              void* d_out, int out_size)
{
    const float* data    = (const float*)d_in[0];
    const float* fc_w    = (const float*)d_in[1];
    const float* fc_b    = (const float*)d_in[2];
    const float* pos_emb = (const float*)d_in[3];
    const float* ln_g    = (const float*)d_in[4];
    const float* ln_b    = (const float*)d_in[5];
    const float* wq      = (const float*)d_in[6];
    const float* wk      = (const float*)d_in[7];
    const float* wv      = (const float*)d_in[8];
    const float* bq      = (const float*)d_in[9];
    const float* bk      = (const float*)d_in[10];
    const float* bv      = (const float*)d_in[11];
    const float* ring_wo = (const float*)d_in[12];
    const float* ring_bo = (const float*)d_in[13];
    const float* star_wo = (const float*)d_in[14];
    const float* star_bo = (const float*)d_in[15];
    float* out = (float*)d_out;

    static bool attr_set = false;
    if (!attr_set) {
        cudaFuncSetAttribute(mma_gemm<0>, cudaFuncAttributeMaxDynamicSharedMemorySize, GEMM_SMEM);
        cudaFuncSetAttribute(mma_gemm<1>, cudaFuncAttributeMaxDynamicSharedMemorySize, GEMM_SMEM);
        cudaFuncSetAttribute(mma_gemm<2>, cudaFuncAttributeMaxDynamicSharedMemorySize, GEMM_SMEM);
        attr_set = true;
    }

    const int M_full = BB * LL;    // 16384
    const int M_xy   = BB * LP1;   // 16392
    const dim3 gFull(4, M_full / 128);              // (4,128)
    const dim3 gQKV (4, (M_xy + 127) / 128, 3);     // (4,129,3)

    // one-time per-call conversions
    wconv_kernel<<<dim3(16, 16, NSLOT), dim3(32, 8)>>>(fc_w, wq, wk, wv, ring_wo);
    aconv_kernel<<<4096, 256>>>(data);

    // embedding: nodes = data @ fc_w + fc_b + pos_emb
    mma_gemm<0><<<gFull, 256, GEMM_SMEM>>>(0, M_full, fc_b, nullptr, nullptr, pos_emb);

    colmean_partial<<<dim3(BB, 16), HH>>>();
    colmean_final<<<BB, HH>>>();

    for (int i = 0; i < NL; ++i) {
        const int wOff = i * HH * HH;
        const int bOff = i * HH;

        ln_concat_kernel<<<M_xy, 128>>>(ln_g + bOff, ln_b + bOff);

        mma_gemm<1><<<gQKV, 256, GEMM_SMEM>>>(i, M_xy, bq + bOff, bk + bOff,
                                              bv + bOff, nullptr);

        ring_attn_kernel<<<(BB * LL * NHD) / 8, 256>>>();

        mma_gemm<2><<<gFull, 256, GEMM_SMEM>>>(i, M_full, ring_bo + bOff,
                                               nullptr, nullptr, nullptr);

        star_attn_kernel<<<BB * NHD, 256>>>();
        star_out_kernel<<<BB, HH>>>(star_wo + wOff, star_bo + bOff);
    }

    maxred_partial<<<dim3(BB, 16), HH>>>();
    final_out_kernel<<<BB, HH>>>(out);
}